// round 15
// baseline (speedup 1.0000x reference)
#include <cuda_runtime.h>
#include <cstdint>

constexpr int B = 64;
constexpr int T = 1024;
constexpr int V = 512;
constexpr int L = 128;
constexpr int NW      = 9;            // 8 producer warps + 1 consumer warp
constexpr int THREADS = NW * 32;      // 288
constexpr int RB      = 4;            // SMEM ring slots (blocks of 8 rows)

#define FULLM  0xffffffffu
#define LOG2E  1.4426950408889634f
#define LN2    0.6931471805599453f

__device__ float g_loss[B];
__device__ int   g_ctr = 0;

__device__ __forceinline__ float ex2f(float x) {
    float y; asm("ex2.approx.f32 %0, %1;" : "=f"(y) : "f"(x)); return y;
}
__device__ __forceinline__ float lg2f(float x) {
    float y; asm("lg2.approx.f32 %0, %1;" : "=f"(y) : "f"(x)); return y;
}
__device__ __forceinline__ float lse2log(float a, float b) {
    const float m  = fmaxf(a, b);
    const float mn = fminf(a, b);
    return m + lg2f(1.0f + ex2f(mn - m));
}

#define BAR_SYNC(ID)   asm volatile("bar.sync %0, %1;"   ::"r"(ID), "n"(THREADS) : "memory")
#define BAR_ARRIVE(ID) asm volatile("bar.arrive %0, %1;" ::"r"(ID), "n"(THREADS) : "memory")

__global__ __launch_bounds__(THREADS, 1)
void ctc_fused(const float* __restrict__ outputs,
               const int*   __restrict__ labels,
               const int*   __restrict__ output_lengths,
               const int*   __restrict__ label_lengths,
               float* __restrict__ out) {
    __shared__ __align__(16) float  stage[8][V];        // 16 KB row staging
    __shared__ __align__(16) float4 ring[RB][8][32];    // 16 KB emit-ratio ring
    __shared__ float lb2s[T];                           // 4 KB blank log2 per row

    const int b    = blockIdx.x;
    const int tid  = threadIdx.x;
    const int lane = tid & 31;
    const int w    = tid >> 5;

    const int olen = output_lengths[b];
    const int llen = label_lengths[b];
    const int tcap = olen - 1;
    const int* lb  = labels + b * L;

    if (w < 8) {
        // ============================ PRODUCERS ============================
        const int c0 = __ldg(lb + 4 * lane),     c1 = __ldg(lb + 4 * lane + 1);
        const int c2 = __ldg(lb + 4 * lane + 2), c3 = __ldg(lb + 4 * lane + 3);
        float* st = stage[w];
        float4* st4 = (float4*)st;

        for (int g = 0; g < 128; ++g) {
            const int s = g & 3;
            if (g >= RB) BAR_SYNC(5 + s);            // wait: consumer freed slot
            const int r = 8 * g + w;                 // row 0..1023
            const float4* rp4 = (const float4*)(outputs + ((size_t)b * T + r) * V);
            const float4 v0 = __ldg(rp4 + lane);
            const float4 v1 = __ldg(rp4 + lane + 32);
            const float4 v2 = __ldg(rp4 + lane + 64);
            const float4 v3 = __ldg(rp4 + lane + 96);
            st4[lane]      = v0;
            st4[lane + 32] = v1;
            st4[lane + 64] = v2;
            st4[lane + 96] = v3;
            __syncwarp();
            const float bl = st[0];
            float4 o;
            o.x = ex2f((st[c0] - bl) * LOG2E);
            o.y = ex2f((st[c1] - bl) * LOG2E);
            o.z = ex2f((st[c2] - bl) * LOG2E);
            o.w = ex2f((st[c3] - bl) * LOG2E);
            ring[s][w][lane] = o;
            if (lane == 0) lb2s[r] = bl * LOG2E;
            __syncwarp();                             // stage reads done before next fill
            __threadfence_block();                    // STS visible before arrive
            BAR_ARRIVE(1 + s);                        // slot filled
        }
        return;
    }

    // ============================ CONSUMER (warp 8) ============================
    const int s0g = 2 * llen - 1;            // odd final state
    const int s1g = 2 * llen;                // even final state (or 256)

    float s0, s1, s2, s3;                    // skip weights as 0/1 floats
    {
        const int li0 = 4 * lane;
        const int c0 = __ldg(lb + li0), c1 = __ldg(lb + li0 + 1);
        const int c2 = __ldg(lb + li0 + 2), c3 = __ldg(lb + li0 + 3);
        s0 = ((li0 > 0) && (c0 != __ldg(lb + li0 - 1))) ? 1.0f : 0.0f;
        s1 = (c1 != c0) ? 1.0f : 0.0f;
        s2 = (c2 != c1) ? 1.0f : 0.0f;
        s3 = (c3 != c2) ? 1.0f : 0.0f;
    }

    const bool o0_0 = (s0g == 8 * lane + 1), o0_1 = (s0g == 8 * lane + 3);
    const bool o0_2 = (s0g == 8 * lane + 5), o0_3 = (s0g == 8 * lane + 7);
    const bool o1_0 = (s1g == 8 * lane),     o1_1 = (s1g == 8 * lane + 2);
    const bool o1_2 = (s1g == 8 * lane + 4), o1_3 = (s1g == 8 * lane + 6);
    const bool oC   = (lane == 31) && (s1g == 256);
    const bool own0 = o0_0 || o0_1 || o0_2 || o0_3;
    const bool own1 = o1_0 || o1_1 || o1_2 || o1_3 || oC;

    float a0=0,a1=0,a2=0,a3=0,a4=0,a5=0,a6=0,a7=0, C=0;
    int   cum = 32;
    float cap0 = 1.0f, cap1 = 1.0f;
    int   capE0 = 0, capE1 = 0;
    float4 e[8];

    BAR_SYNC(1 + 0);                          // slot 0 (rows 0..7) filled
    {   // ---- t = 0 init (scaled 2^-32) ----
        const float h  = __uint_as_float((unsigned)(127 - 32) << 23);
        const float r0 = ring[0][0][0].x;     // ratio(row 0, label 0)
        if (lane == 0) { a0 = h; a1 = r0 * h; }
        if (tcap == 0) {
            cap0 = o0_0 ? a1 : cap0;
            cap1 = o1_0 ? a0 : cap1;
            capE0 = cum; capE1 = cum;
        }
    }
    #pragma unroll
    for (int k = 1; k < 8; ++k) e[k] = ring[0][k][lane];

    float b7pipe = __shfl_up_sync(FULLM, a7, 1);

    #define CTC_STEP(K_, TB_, BS0_, CAPF_)                                        \
    {                                                                             \
        const float b7n = b7pipe * (BS0_);                                        \
        const float4 e4 = e[K_];                                                  \
        C  = C + a7;                                                              \
        const float a7n = (a7 + fmaf(s3, a5, a6)) * e4.w;                         \
        b7pipe = __shfl_up_sync(FULLM, a7n, 1);                                   \
        a6 = a6 + a5;                                                             \
        a5 = (a5 + fmaf(s2, a3, a4 )) * e4.z;                                     \
        a4 = a4 + a3;                                                             \
        a3 = (a3 + fmaf(s1, a1, a2 )) * e4.y;                                     \
        a2 = a2 + a1;                                                             \
        a1 = (a1 + fmaf(s0, b7n, a0)) * e4.x;                                     \
        a0 = a0 + b7n;                                                            \
        a7 = a7n;                                                                 \
        if (CAPF_) {                                                              \
            const bool pc  = ((TB_) + (K_) == tcap);                              \
            const bool h0  = pc && own0;                                          \
            const bool h1  = pc && own1;                                          \
            const float v0 = o0_0 ? a1 : (o0_1 ? a3 : (o0_2 ? a5 : a7));          \
            const float v1 = o1_0 ? a0 : (o1_1 ? a2 :                             \
                             (o1_2 ? a4 : (oC ? C : a6)));                        \
            cap0  = h0 ? v0  : cap0;  cap1  = h1 ? v1  : cap1;                    \
            capE0 = h0 ? cum : capE0; capE1 = h1 ? cum : capE1;                   \
        }                                                                         \
    }

    #define CTC_RENORM()                                                          \
    {                                                                             \
        const float mx = fmaxf(fmaxf(fmaxf(a0, a1), fmaxf(a2, a3)),               \
                               fmaxf(fmaxf(a4, a5), fmaxf(a6, fmaxf(a7, C))));    \
        const int ee   = (int)((__float_as_uint(mx) >> 23) & 0xffu);              \
        int radj = ee - 95;                                                       \
        radj = (radj < -95) ? -95 : radj;                                         \
        radj = (radj > 126) ? 126 : radj;                                         \
        const float sf = __uint_as_float((unsigned)(127 - radj) << 23);           \
        a0*=sf; a1*=sf; a2*=sf; a3*=sf; a4*=sf; a5*=sf; a6*=sf; a7*=sf; C*=sf;    \
        cum += radj;                                                              \
    }

    {   // ---- block 0: steps t = 1..7 (bscale = 1, cum uniform) ----
        const float bs0 = (lane == 0) ? 0.0f : 1.0f;
        if ((unsigned)(tcap - 1) < 7u) {
            #pragma unroll
            for (int k = 1; k < 8; ++k) CTC_STEP(k, 0, bs0, true)
        } else {
            #pragma unroll
            for (int k = 1; k < 8; ++k) CTC_STEP(k, 0, bs0, false)
        }
        CTC_RENORM()
    }
    BAR_ARRIVE(5 + 0);                        // slot 0 free

    // ---- main blocks g = 1..127: rows 8g..8g+7 = steps t = 8g..8g+7 ----
    for (int g = 1; g < 128; ++g) {
        const int s = g & 3;
        BAR_SYNC(1 + s);                      // slot filled
        #pragma unroll
        for (int k = 0; k < 8; ++k) e[k] = ring[s][k][lane];

        // block top: branchless cross-lane scale alignment
        const int  cumP  = __shfl_up_sync(FULLM, cum, 1);
        int        db    = cumP - cum;
        const bool adopt = (lane > 0) && (db > 40);
        a0 = adopt ? 0.0f : a0;  a1 = adopt ? 0.0f : a1;
        a2 = adopt ? 0.0f : a2;  a3 = adopt ? 0.0f : a3;
        a4 = adopt ? 0.0f : a4;  a5 = adopt ? 0.0f : a5;
        a6 = adopt ? 0.0f : a6;  a7 = adopt ? 0.0f : a7;
        C  = adopt ? 0.0f : C;
        cum = adopt ? cumP : cum;
        db  = adopt ? 0 : db;
        db  = (db < -126) ? -126 : db;
        const float bscale = __uint_as_float((unsigned)(127 + db) << 23);
        const float bs0    = (lane == 0) ? 0.0f : bscale;
        b7pipe = __shfl_up_sync(FULLM, a7, 1);

        const int tb = 8 * g;
        if ((unsigned)(tcap - tb) < 8u) {
            #pragma unroll
            for (int k = 0; k < 8; ++k) CTC_STEP(k, tb, bs0, true)
        } else {
            #pragma unroll
            for (int k = 0; k < 8; ++k) CTC_STEP(k, tb, bs0, false)
        }
        CTC_RENORM()
        BAR_ARRIVE(5 + s);                    // slot free
    }
    #undef CTC_STEP
    #undef CTC_RENORM

    // ---- epilogue: blank-log sum (deterministic) + cap gather via shfl ----
    float S = 0.0f;
    #pragma unroll 8
    for (int i = lane; i < T; i += 32)
        S += (i <= tcap) ? lb2s[i] : 0.0f;
    #pragma unroll
    for (int o = 16; o > 0; o >>= 1)
        S += __shfl_xor_sync(FULLM, S, o);

    const int src0 = s0g >> 3;
    int src1 = s1g >> 3; src1 = (src1 > 31) ? 31 : src1;
    const float f0 = __shfl_sync(FULLM, cap0, src0);
    const float f1 = __shfl_sync(FULLM, cap1, src1);
    const int   x0 = __shfl_sync(FULLM, capE0, src0);
    const int   x1 = __shfl_sync(FULLM, capE1, src1);

    if (lane == 0) {
        const float l0 = lg2f(f0) + (float)x0 + S;
        const float l1 = lg2f(f1) + (float)x1 + S;
        const float ll = lse2log(l0, l1) * LN2;
        g_loss[b] = -ll / (float)llen;
        __threadfence();
        const int old = atomicAdd(&g_ctr, 1);
        if (old == B - 1) {
            __threadfence();
            float acc = 0.0f;
            #pragma unroll 8
            for (int i = 0; i < B; ++i) acc += g_loss[i];
            *out = acc * (1.0f / (float)B);
            g_ctr = 0;   // reset for next graph replay
        }
    }
}

extern "C" void kernel_launch(void* const* d_in, const int* in_sizes, int n_in,
                              void* d_out, int out_size) {
    const float* outputs        = (const float*)d_in[0];
    const int*   labels         = (const int*)d_in[1];
    const int*   output_lengths = (const int*)d_in[2];
    const int*   label_lengths  = (const int*)d_in[3];
    float* out = (float*)d_out;

    ctc_fused<<<B, THREADS>>>(outputs, labels, output_lengths,
                              label_lengths, out);
}